// round 7
// baseline (speedup 1.0000x reference)
#include <cuda_runtime.h>
#include <cuda_bf16.h>
#include <math.h>
#include <stdint.h>

#define TM      128
#define KNB     27
#define MAXN    150000

// ---- per-stage smem: A hi 16K | A lo 16K | W hi 8K | W lo 8K = 48KB ----
#define OFF_AH   0
#define OFF_AL   16384
#define OFF_WH   32768
#define OFF_WL   40960
#define STAGE    49152
#define SMEM_BYTES (2 * STAGE)      // 96KB -> 2 blocks/SM

// ------------------------- device scratch -------------------------
// f32 scratch for G / H (reused across stages)
__device__ float g_Gf[(size_t)MAXN * 64];
__device__ float g_Hf[(size_t)MAXN * 64];
// bf16 gather tables: row n = 256B: 64 bf16 hi | 64 bf16 lo
__device__ __align__(16) char g_x2b[(size_t)MAXN * 256];
__device__ __align__(16) char g_hgb[(size_t)MAXN * 256];
__device__ __align__(16) char g_hhb[(size_t)MAXN * 256];
__device__ __align__(16) char g_y1b[(size_t)MAXN * 256];
// transposed neighbor index: [k][n]
__device__ int g_idxT[KNB * MAXN];
// conv weight planes (8 tensors x 27 planes of 64x64 bf16), hi/lo, pre-swizzled
__device__ __align__(16) __nv_bfloat16 g_wch[8 * 27 * 4096];
__device__ __align__(16) __nv_bfloat16 g_wcl[8 * 27 * 4096];
// dense weight planes (4 tensors)
__device__ __align__(16) __nv_bfloat16 g_wdh[4 * 4096];
__device__ __align__(16) __nv_bfloat16 g_wdl[4 * 4096];

// ------------------------- helpers -------------------------
__device__ __forceinline__ uint32_t smem_u32(const void* p) {
    uint32_t a;
    asm("{ .reg .u64 t; cvta.to.shared.u64 t, %1; cvt.u32.u64 %0, t; }" : "=r"(a) : "l"(p));
    return a;
}
__device__ __forceinline__ float lrelu(float v) { return v >= 0.f ? v : 0.2f * v; }

__device__ __forceinline__ uint32_t pack_bf2(float lo_elem, float hi_elem) {
    uint32_t r;
    asm("cvt.rn.bf16x2.f32 %0, %1, %2;" : "=r"(r) : "f"(hi_elem), "f"(lo_elem));
    return r;
}
__device__ __forceinline__ float bflo_f(uint32_t u) { return __uint_as_float(u << 16); }
__device__ __forceinline__ float bfhi_f(uint32_t u) { return __uint_as_float(u & 0xFFFF0000u); }

__device__ __forceinline__ void cp16(uint32_t dst, const char* src) {
    asm volatile("cp.async.cg.shared.global [%0], [%1], 16;" :: "r"(dst), "l"(src));
}
#define CP_COMMIT() asm volatile("cp.async.commit_group;" ::: "memory")
#define CP_WAIT0()  asm volatile("cp.async.wait_group 0;" ::: "memory")
#define CP_WAIT1()  asm volatile("cp.async.wait_group 1;" ::: "memory")

__device__ __forceinline__ void ldsm4(uint32_t* r, uint32_t a) {
    asm volatile("ldmatrix.sync.aligned.m8n8.x4.shared.b16 {%0,%1,%2,%3}, [%4];"
                 : "=r"(r[0]), "=r"(r[1]), "=r"(r[2]), "=r"(r[3]) : "r"(a));
}
__device__ __forceinline__ void ldsm4t(uint32_t* r, uint32_t a) {
    asm volatile("ldmatrix.sync.aligned.m8n8.x4.trans.shared.b16 {%0,%1,%2,%3}, [%4];"
                 : "=r"(r[0]), "=r"(r[1]), "=r"(r[2]), "=r"(r[3]) : "r"(a));
}
__device__ __forceinline__ void mma_bf16(float* d, const uint32_t* a, const uint32_t* b) {
    asm volatile(
        "mma.sync.aligned.m16n8k16.row.col.f32.bf16.bf16.f32 "
        "{%0,%1,%2,%3}, {%4,%5,%6,%7}, {%8,%9}, {%0,%1,%2,%3};"
        : "+f"(d[0]), "+f"(d[1]), "+f"(d[2]), "+f"(d[3])
        : "r"(a[0]), "r"(a[1]), "r"(a[2]), "r"(a[3]), "r"(b[0]), "r"(b[1]));
}

// ------------------------- prep kernels -------------------------
// weight planes: [kk][n], 128B rows, 16B chunk index XOR (kk & 7); hi/lo split
__global__ void kprep_conv(const float* w0, const float* w1, const float* w2,
                           const float* w3, const float* w4, const float* w5,
                           const float* w6, const float* w7) {
    int e = blockIdx.x * 256 + threadIdx.x;
    const int per = 27 * 4096;
    if (e >= 8 * per) return;
    int ti = e / per;
    int r  = e % per;
    int k  = r >> 12;
    int p  = r & 4095;
    int kk = p >> 6;
    int n  = p & 63;
    const float* ws[8] = {w0, w1, w2, w3, w4, w5, w6, w7};
    float v = ws[ti][(size_t)k * 4096 + kk * 64 + n];
    __nv_bfloat16 bh = __float2bfloat16_rn(v);
    __nv_bfloat16 bl = __float2bfloat16_rn(v - __bfloat162float(bh));
    int off = kk * 128 + (((n >> 3) ^ (kk & 7)) << 4) + (n & 7) * 2;
    size_t base = ((size_t)ti * 27 + k) * 8192;
    *(__nv_bfloat16*)((char*)g_wch + base + off) = bh;
    *(__nv_bfloat16*)((char*)g_wcl + base + off) = bl;
}

__global__ void kprep_dense(const float* w0, const float* w1,
                            const float* w2, const float* w3) {
    int e = blockIdx.x * 256 + threadIdx.x;
    if (e >= 4 * 4096) return;
    int ti = e >> 12;
    int p  = e & 4095;
    int kk = p >> 6;
    int n  = p & 63;
    const float* ws[4] = {w0, w1, w2, w3};
    float v = ws[ti][kk * 64 + n];
    __nv_bfloat16 bh = __float2bfloat16_rn(v);
    __nv_bfloat16 bl = __float2bfloat16_rn(v - __bfloat162float(bh));
    int off = kk * 128 + (((n >> 3) ^ (kk & 7)) << 4) + (n & 7) * 2;
    size_t base = (size_t)ti * 8192;
    *(__nv_bfloat16*)((char*)g_wdh + base + off) = bh;
    *(__nv_bfloat16*)((char*)g_wdl + base + off) = bl;
}

__global__ void kprep_idx(const int* __restrict__ idx, int N) {
    int e = blockIdx.x * 256 + threadIdx.x;
    if (e >= N * KNB) return;
    int n = e / KNB, k = e % KNB;
    g_idxT[(size_t)k * N + n] = idx[e];
}

// x2 (cols 64..127 of x, stride 128) -> bf16 hi/lo table
__global__ void kprep_x2(const float* __restrict__ x, int N) {
    int e = blockIdx.x * 256 + threadIdx.x;
    if (e >= N * 32) return;
    int n = e >> 5, c = (e & 31) * 2;
    float v0 = x[(size_t)n * 128 + 64 + c];
    float v1 = x[(size_t)n * 128 + 64 + c + 1];
    uint32_t hp = pack_bf2(v0, v1);
    uint32_t lp = pack_bf2(v0 - bflo_f(hp), v1 - bfhi_f(hp));
    *(uint32_t*)(g_x2b + (size_t)n * 256 + c * 2) = hp;
    *(uint32_t*)(g_x2b + (size_t)n * 256 + 128 + c * 2) = lp;
}

// ------------------------- cp.async staging (128 threads) -----------------
// gather 128 bf16 rows (hi+lo) into a swizzled A tile pair; thread t = row t
__device__ __forceinline__ void gather_cp(uint32_t dH, uint32_t dL,
    const char* __restrict__ tab, const int* __restrict__ idxT,
    int k, int nbase, int N, int t)
{
    int n = nbase + t; if (n >= N) n = N - 1;
    size_t g = (size_t)idxT[(size_t)k * N + n] * 256;
    const int rx = (t & 7);
#pragma unroll
    for (int c = 0; c < 8; ++c) {
        int sw = t * 128 + ((c ^ rx) << 4);
        cp16(dH + sw, tab + g + c * 16);
        cp16(dL + sw, tab + g + 128 + c * 16);
    }
}
// stage one 16KB (hi 8K + lo 8K) pre-swizzled weight plane
__device__ __forceinline__ void stageW_cp(uint32_t dst,
    const __nv_bfloat16* wh, const __nv_bfloat16* wl, int t)
{
#pragma unroll
    for (int i = 0; i < 4; ++i) {
        cp16(dst + (t + i * 128) * 16,        (const char*)wh + (t + i * 128) * 16);
        cp16(dst + 8192 + (t + i * 128) * 16, (const char*)wl + (t + i * 128) * 16);
    }
}

// ------------------------- MMA core (round-4 verified) -------------------
// warp wl computes rows [wl*32, wl*32+32) x 64 cols of the 128x64 tile
__device__ __forceinline__ void mma_block(float acc[2][8][4],
    uint32_t aHi, uint32_t aLo, uint32_t bHi, uint32_t bLo,
    int wl, int lr, int lc)
{
    const int arow = (wl * 32 + lr) * 128;
    const int axor = lr & 7;
#pragma unroll
    for (int ks = 0; ks < 4; ++ks) {
        uint32_t ah[2][4], al[2][4];
        const int ac = ((ks * 2 + lc) ^ axor) << 4;
#pragma unroll
        for (int mt = 0; mt < 2; ++mt) {
            uint32_t ad = arow + mt * 2048 + ac;
            ldsm4(ah[mt], aHi + ad);
            ldsm4(al[mt], aLo + ad);
        }
        const int brow = ks * 2048 + lr * 128;
#pragma unroll
        for (int np = 0; np < 4; ++np) {
            uint32_t bd = brow + (((2 * np + lc) ^ axor) << 4);
            uint32_t bh[4], bl[4];
            ldsm4t(bh, bHi + bd);
            ldsm4t(bl, bLo + bd);
#pragma unroll
            for (int mt = 0; mt < 2; ++mt) {
#pragma unroll
                for (int j = 0; j < 2; ++j) {
                    float* d = acc[mt][np * 2 + j];
                    mma_bf16(d, ah[mt], &bh[j * 2]);
                    mma_bf16(d, al[mt], &bh[j * 2]);
                    mma_bf16(d, ah[mt], &bl[j * 2]);
                }
            }
        }
    }
}

// write lrelu(acc) as bf16 hi/lo swizzled A tiles (smem)
__device__ __forceinline__ void acc_to_tiles(char* sm, int baseH, int baseL,
    float acc[2][8][4], int wl, int gID, int tig)
{
#pragma unroll
    for (int mt = 0; mt < 2; ++mt) {
        int r0 = wl * 32 + mt * 16 + gID;
        int r1 = r0 + 8;
#pragma unroll
        for (int nt = 0; nt < 8; ++nt) {
            float e0 = lrelu(acc[mt][nt][0]), e1 = lrelu(acc[mt][nt][1]);
            float e2 = lrelu(acc[mt][nt][2]), e3 = lrelu(acc[mt][nt][3]);
            uint32_t h0 = pack_bf2(e0, e1);
            uint32_t l0 = pack_bf2(e0 - bflo_f(h0), e1 - bfhi_f(h0));
            uint32_t h1 = pack_bf2(e2, e3);
            uint32_t l1 = pack_bf2(e2 - bflo_f(h1), e3 - bfhi_f(h1));
            int b0 = r0 * 128 + ((nt ^ (r0 & 7)) << 4) + tig * 4;
            int b1 = r1 * 128 + ((nt ^ (r1 & 7)) << 4) + tig * 4;
            *(uint32_t*)(sm + baseH + b0) = h0;
            *(uint32_t*)(sm + baseL + b0) = l0;
            *(uint32_t*)(sm + baseH + b1) = h1;
            *(uint32_t*)(sm + baseL + b1) = l1;
        }
    }
}

// the k-loop shared by both conv kernels
__device__ __forceinline__ void conv_loop(float acc[2][8][4],
    char* sm, uint32_t sb,
    const char* __restrict__ tab, const int* __restrict__ idxT,
    const __nv_bfloat16* __restrict__ wh, const __nv_bfloat16* __restrict__ wl_,
    int nbase, int N, int t, int wl, int lr, int lc)
{
    gather_cp(sb + OFF_AH, sb + OFF_AL, tab, idxT, 0, nbase, N, t);
    stageW_cp(sb + OFF_WH, wh, wl_, t);
    CP_COMMIT();
    for (int k = 0; k < KNB; ++k) {
        const uint32_t cur = (uint32_t)(k & 1) * STAGE;
        const uint32_t nxt = (uint32_t)((k + 1) & 1) * STAGE;
        if (k + 1 < KNB) {
            gather_cp(sb + nxt + OFF_AH, sb + nxt + OFF_AL, tab, idxT, k + 1, nbase, N, t);
            stageW_cp(sb + nxt + OFF_WH, wh + (k + 1) * 4096, wl_ + (k + 1) * 4096, t);
            CP_COMMIT();
            CP_WAIT1();
        } else {
            CP_WAIT0();
        }
        __syncthreads();
        mma_block(acc, sb + cur + OFF_AH, sb + cur + OFF_AL,
                  sb + cur + OFF_WH, sb + cur + OFF_WL, wl, lr, lc);
        __syncthreads();
    }
}

// ---------------------------------------------------------------------------
// kgconv_hidden: one branch per blockIdx.y.
//   out_table = lrelu( lrelu( sum_k gather(srcTab) @ W1[k] ) @ W2 )  (bf16 hi/lo)
// ---------------------------------------------------------------------------
__global__ __launch_bounds__(128, 2)
void kgconv_hidden(const char* __restrict__ srcTab, const int* __restrict__ idxT,
                   const __nv_bfloat16* w1gh, const __nv_bfloat16* w1gl,
                   const __nv_bfloat16* w1hh, const __nv_bfloat16* w1hl,
                   const __nv_bfloat16* w2gh, const __nv_bfloat16* w2gl,
                   const __nv_bfloat16* w2hh, const __nv_bfloat16* w2hl,
                   char* __restrict__ outg, char* __restrict__ outh, int N)
{
    extern __shared__ char sm[];
    const uint32_t sb = smem_u32(sm);
    const int t = threadIdx.x;
    const int lane = t & 31, wl = t >> 5;
    const int lr = ((lane >> 3) & 1) * 8 + (lane & 7);
    const int lc = lane >> 4;
    const int gID = lane >> 2, tig = lane & 3;
    const int nbase = blockIdx.x * TM;
    const int br = blockIdx.y;

    const __nv_bfloat16* w1h = br ? w1hh : w1gh;
    const __nv_bfloat16* w1l = br ? w1hl : w1gl;
    const __nv_bfloat16* w2h = br ? w2hh : w2gh;
    const __nv_bfloat16* w2l = br ? w2hl : w2gl;
    char* outb = br ? outh : outg;

    float acc[2][8][4];
#pragma unroll
    for (int mt = 0; mt < 2; ++mt)
#pragma unroll
        for (int nt = 0; nt < 8; ++nt)
#pragma unroll
            for (int q = 0; q < 4; ++q) acc[mt][nt][q] = 0.f;

    conv_loop(acc, sm, sb, srcTab, idxT, w1h, w1l, nbase, N, t, wl, lr, lc);

    // hidden = lrelu(conv1) -> buf1 A tiles; W2 -> buf1 W
    acc_to_tiles(sm, STAGE + OFF_AH, STAGE + OFF_AL, acc, wl, gID, tig);
    stageW_cp(sb + STAGE + OFF_WH, w2h, w2l, t);
    CP_COMMIT();
    CP_WAIT0();
    __syncthreads();

#pragma unroll
    for (int mt = 0; mt < 2; ++mt)
#pragma unroll
        for (int nt = 0; nt < 8; ++nt)
#pragma unroll
            for (int q = 0; q < 4; ++q) acc[mt][nt][q] = 0.f;

    mma_block(acc, sb + STAGE + OFF_AH, sb + STAGE + OFF_AL,
              sb + STAGE + OFF_WH, sb + STAGE + OFF_WL, wl, lr, lc);

    // store lrelu(hidden2) as bf16 hi/lo table (256B rows)
#pragma unroll
    for (int mt = 0; mt < 2; ++mt) {
        int n0 = nbase + wl * 32 + mt * 16 + gID;
        int n1 = n0 + 8;
#pragma unroll
        for (int nt = 0; nt < 8; ++nt) {
            int c = nt * 8 + tig * 2;
            float e0 = lrelu(acc[mt][nt][0]), e1 = lrelu(acc[mt][nt][1]);
            float e2 = lrelu(acc[mt][nt][2]), e3 = lrelu(acc[mt][nt][3]);
            if (n0 < N) {
                uint32_t hp = pack_bf2(e0, e1);
                uint32_t lp = pack_bf2(e0 - bflo_f(hp), e1 - bfhi_f(hp));
                *(uint32_t*)(outb + (size_t)n0 * 256 + c * 2) = hp;
                *(uint32_t*)(outb + (size_t)n0 * 256 + 128 + c * 2) = lp;
            }
            if (n1 < N) {
                uint32_t hp = pack_bf2(e2, e3);
                uint32_t lp = pack_bf2(e2 - bflo_f(hp), e3 - bfhi_f(hp));
                *(uint32_t*)(outb + (size_t)n1 * 256 + c * 2) = hp;
                *(uint32_t*)(outb + (size_t)n1 * 256 + 128 + c * 2) = lp;
            }
        }
    }
}

// ---------------------------------------------------------------------------
// kgconv_f32: one branch per blockIdx.y; out = sum_k gather(tab) @ W3[k] (f32)
// ---------------------------------------------------------------------------
__global__ __launch_bounds__(128, 2)
void kgconv_f32(const char* __restrict__ tg, const char* __restrict__ th,
                const int* __restrict__ idxT,
                const __nv_bfloat16* w3gh, const __nv_bfloat16* w3gl,
                const __nv_bfloat16* w3hh, const __nv_bfloat16* w3hl,
                float* __restrict__ Gout, float* __restrict__ Hout, int N)
{
    extern __shared__ char sm[];
    const uint32_t sb = smem_u32(sm);
    const int t = threadIdx.x;
    const int lane = t & 31, wl = t >> 5;
    const int lr = ((lane >> 3) & 1) * 8 + (lane & 7);
    const int lc = lane >> 4;
    const int gID = lane >> 2, tig = lane & 3;
    const int nbase = blockIdx.x * TM;
    const int br = blockIdx.y;

    const char* tab = br ? th : tg;
    const __nv_bfloat16* wh = br ? w3hh : w3gh;
    const __nv_bfloat16* wl_ = br ? w3hl : w3gl;
    float* outp = br ? Hout : Gout;

    float acc[2][8][4];
#pragma unroll
    for (int mt = 0; mt < 2; ++mt)
#pragma unroll
        for (int nt = 0; nt < 8; ++nt)
#pragma unroll
            for (int q = 0; q < 4; ++q) acc[mt][nt][q] = 0.f;

    conv_loop(acc, sm, sb, tab, idxT, wh, wl_, nbase, N, t, wl, lr, lc);

    // store acc f32 (dense N x 64)
#pragma unroll
    for (int mt = 0; mt < 2; ++mt) {
        int n0 = nbase + wl * 32 + mt * 16 + gID;
        int n1 = n0 + 8;
#pragma unroll
        for (int nt = 0; nt < 8; ++nt) {
            int c = nt * 8 + tig * 2;
            if (n0 < N)
                *(float2*)(outp + (size_t)n0 * 64 + c) =
                    make_float2(acc[mt][nt][0], acc[mt][nt][1]);
            if (n1 < N)
                *(float2*)(outp + (size_t)n1 * 64 + c) =
                    make_float2(acc[mt][nt][2], acc[mt][nt][3]);
        }
    }
}

// ---------------------------------------------------------------------------
// kepilog: out[n,c] = x[n,c] * exp(tanh(G[n,c]/2)) + H[n,c]; optional bf16 table
// x/out row stride 128 (column block pre-offset by caller)
// ---------------------------------------------------------------------------
__global__ void kepilog(const float* __restrict__ G, const float* __restrict__ H,
                        const float* __restrict__ xpart, float* __restrict__ outp,
                        char* __restrict__ bfout, int N)
{
    int e = blockIdx.x * 256 + threadIdx.x;
    if (e >= N * 16) return;
    int n = e >> 4, q = (e & 15) * 4;
    float4 gv = *(const float4*)(G + (size_t)n * 64 + q);
    float4 hv = *(const float4*)(H + (size_t)n * 64 + q);
    float4 xv = *(const float4*)(xpart + (size_t)n * 128 + q);
    float4 y;
    y.x = fmaf(xv.x, expf(tanhf(0.5f * gv.x)), hv.x);
    y.y = fmaf(xv.y, expf(tanhf(0.5f * gv.y)), hv.y);
    y.z = fmaf(xv.z, expf(tanhf(0.5f * gv.z)), hv.z);
    y.w = fmaf(xv.w, expf(tanhf(0.5f * gv.w)), hv.w);
    *(float4*)(outp + (size_t)n * 128 + q) = y;
    if (bfout) {
        uint32_t h0 = pack_bf2(y.x, y.y), h1 = pack_bf2(y.z, y.w);
        uint32_t l0 = pack_bf2(y.x - bflo_f(h0), y.y - bfhi_f(h0));
        uint32_t l1 = pack_bf2(y.z - bflo_f(h1), y.w - bfhi_f(h1));
        *(uint2*)(bfout + (size_t)n * 256 + q * 2) = make_uint2(h0, h1);
        *(uint2*)(bfout + (size_t)n * 256 + 128 + q * 2) = make_uint2(l0, l1);
    }
}

// ---------------------------------------------------------------------------
extern "C" void kernel_launch(void* const* d_in, const int* in_sizes, int n_in,
                              void* d_out, int out_size)
{
    const float* x     = (const float*)d_in[0];
    const int*   nbr   = (const int*)d_in[1];
    const float* g1_w1 = (const float*)d_in[2];
    const float* g1_w2 = (const float*)d_in[3];
    const float* g1_w3 = (const float*)d_in[4];
    const float* g2_w1 = (const float*)d_in[5];
    const float* g2_w2 = (const float*)d_in[6];
    const float* g2_w3 = (const float*)d_in[7];
    const float* h1_w1 = (const float*)d_in[8];
    const float* h1_w2 = (const float*)d_in[9];
    const float* h1_w3 = (const float*)d_in[10];
    const float* h2_w1 = (const float*)d_in[11];
    const float* h2_w2 = (const float*)d_in[12];
    const float* h2_w3 = (const float*)d_in[13];
    float* out = (float*)d_out;

    const int N = in_sizes[1] / KNB;
    const int blocks = (N + TM - 1) / TM;

    cudaFuncSetAttribute(kgconv_hidden, cudaFuncAttributeMaxDynamicSharedMemorySize, SMEM_BYTES);
    cudaFuncSetAttribute(kgconv_f32,    cudaFuncAttributeMaxDynamicSharedMemorySize, SMEM_BYTES);

    __nv_bfloat16 *wch, *wcl, *wdh, *wdl;
    cudaGetSymbolAddress((void**)&wch, g_wch);
    cudaGetSymbolAddress((void**)&wcl, g_wcl);
    cudaGetSymbolAddress((void**)&wdh, g_wdh);
    cudaGetSymbolAddress((void**)&wdl, g_wdl);
    int* idxT;   cudaGetSymbolAddress((void**)&idxT, g_idxT);
    char *x2b, *hgb, *hhb, *y1b;
    cudaGetSymbolAddress((void**)&x2b, g_x2b);
    cudaGetSymbolAddress((void**)&hgb, g_hgb);
    cudaGetSymbolAddress((void**)&hhb, g_hhb);
    cudaGetSymbolAddress((void**)&y1b, g_y1b);
    float *Gf, *Hf;
    cudaGetSymbolAddress((void**)&Gf, g_Gf);
    cudaGetSymbolAddress((void**)&Hf, g_Hf);

    // conv tensor order: 0:g2w1 1:h2w1 2:g2w3 3:h2w3 4:g1w1 5:h1w1 6:g1w3 7:h1w3
    kprep_conv<<<(8 * 27 * 4096 + 255) / 256, 256>>>(
        g2_w1, h2_w1, g2_w3, h2_w3, g1_w1, h1_w1, g1_w3, h1_w3);
    // dense order: 0:g2w2 1:h2w2 2:g1w2 3:h1w2
    kprep_dense<<<(4 * 4096 + 255) / 256, 256>>>(g2_w2, h2_w2, g1_w2, h1_w2);
    kprep_idx<<<(N * KNB + 255) / 256, 256>>>(nbr, N);
    kprep_x2<<<(N * 32 + 255) / 256, 256>>>(x, N);

    const int CP = 27 * 4096;   // bf16 elems per conv tensor
    dim3 grid2(blocks, 2);

    // ---- Stage 1: g2 / h2 bottlenecks on x2 table ----
    kgconv_hidden<<<grid2, 128, SMEM_BYTES>>>(
        x2b, idxT,
        wch + 0 * CP, wcl + 0 * CP, wch + 1 * CP, wcl + 1 * CP,
        wdh + 0 * 4096, wdl + 0 * 4096, wdh + 1 * 4096, wdl + 1 * 4096,
        hgb, hhb, N);
    kgconv_f32<<<grid2, 128, SMEM_BYTES>>>(
        hgb, hhb, idxT,
        wch + 2 * CP, wcl + 2 * CP, wch + 3 * CP, wcl + 3 * CP,
        Gf, Hf, N);
    // y1 = x1 * exp(tanh(G/2)) + H -> out[:, 0:64]  (+ bf16 table for stage 2)
    kepilog<<<(N * 16 + 255) / 256, 256>>>(Gf, Hf, x, out, y1b, N);

    // ---- Stage 2: g1 / h1 bottlenecks on y1 table ----
    kgconv_hidden<<<grid2, 128, SMEM_BYTES>>>(
        y1b, idxT,
        wch + 4 * CP, wcl + 4 * CP, wch + 5 * CP, wcl + 5 * CP,
        wdh + 2 * 4096, wdl + 2 * 4096, wdh + 3 * 4096, wdl + 3 * 4096,
        hgb, hhb, N);
    kgconv_f32<<<grid2, 128, SMEM_BYTES>>>(
        hgb, hhb, idxT,
        wch + 6 * CP, wcl + 6 * CP, wch + 7 * CP, wcl + 7 * CP,
        Gf, Hf, N);
    // y2 = x2 * exp(tanh(G2/2)) + H2 -> out[:, 64:128]
    kepilog<<<(N * 16 + 255) / 256, 256>>>(Gf, Hf, x + 64, out + 64, nullptr, N);
}

// round 8
// speedup vs baseline: 1.5443x; 1.5443x over previous
#include <cuda_runtime.h>
#include <cuda_bf16.h>
#include <math.h>
#include <stdint.h>

#define TM      128
#define KNB     27
#define MAXN    150000

// ---- smem layout (both conv kernels, 96KB, 2 blocks/SM) ----
#define OFF_AH   0            // A tile (kconvA: shared gather / kconvB: g) hi
#define OFF_AL   16384        // .. lo
#define OFF_BH   32768        // kconvA: hidden_h / kconvB: A_h hi
#define OFF_BL   49152        // .. lo
#define OFF_W    65536        // 4 planes x 8KB: [g_hi, g_lo, h_hi, h_lo]
#define SMEM_BYTES 98304

// ------------------------- device scratch -------------------------
// bf16 gather tables: row n = 256B: 64 bf16 hi | 64 bf16 lo
__device__ __align__(16) char g_x2b[(size_t)MAXN * 256];
__device__ __align__(16) char g_hgb[(size_t)MAXN * 256];
__device__ __align__(16) char g_hhb[(size_t)MAXN * 256];
__device__ __align__(16) char g_y1b[(size_t)MAXN * 256];
// transposed neighbor index: [k][n]
__device__ int g_idxT[KNB * MAXN];
// conv weight planes (8 tensors x 27 planes of 64x64 bf16), hi/lo, pre-swizzled
__device__ __align__(16) __nv_bfloat16 g_wch[8 * 27 * 4096];
__device__ __align__(16) __nv_bfloat16 g_wcl[8 * 27 * 4096];
// dense weight planes (4 tensors)
__device__ __align__(16) __nv_bfloat16 g_wdh[4 * 4096];
__device__ __align__(16) __nv_bfloat16 g_wdl[4 * 4096];

// ------------------------- helpers -------------------------
__device__ __forceinline__ uint32_t smem_u32(const void* p) {
    uint32_t a;
    asm("{ .reg .u64 t; cvta.to.shared.u64 t, %1; cvt.u32.u64 %0, t; }" : "=r"(a) : "l"(p));
    return a;
}
__device__ __forceinline__ float lrelu(float v) { return v >= 0.f ? v : 0.2f * v; }

__device__ __forceinline__ uint32_t pack_bf2(float lo_elem, float hi_elem) {
    uint32_t r;
    asm("cvt.rn.bf16x2.f32 %0, %1, %2;" : "=r"(r) : "f"(hi_elem), "f"(lo_elem));
    return r;
}
__device__ __forceinline__ float bflo_f(uint32_t u) { return __uint_as_float(u << 16); }
__device__ __forceinline__ float bfhi_f(uint32_t u) { return __uint_as_float(u & 0xFFFF0000u); }

__device__ __forceinline__ void cp16(uint32_t dst, const char* src) {
    asm volatile("cp.async.cg.shared.global [%0], [%1], 16;" :: "r"(dst), "l"(src));
}
#define CP_COMMIT() asm volatile("cp.async.commit_group;" ::: "memory")
#define CP_WAIT0()  asm volatile("cp.async.wait_group 0;" ::: "memory")

__device__ __forceinline__ void ldsm4(uint32_t* r, uint32_t a) {
    asm volatile("ldmatrix.sync.aligned.m8n8.x4.shared.b16 {%0,%1,%2,%3}, [%4];"
                 : "=r"(r[0]), "=r"(r[1]), "=r"(r[2]), "=r"(r[3]) : "r"(a));
}
__device__ __forceinline__ void ldsm4t(uint32_t* r, uint32_t a) {
    asm volatile("ldmatrix.sync.aligned.m8n8.x4.trans.shared.b16 {%0,%1,%2,%3}, [%4];"
                 : "=r"(r[0]), "=r"(r[1]), "=r"(r[2]), "=r"(r[3]) : "r"(a));
}
__device__ __forceinline__ void mma_bf16(float* d, const uint32_t* a, const uint32_t* b) {
    asm volatile(
        "mma.sync.aligned.m16n8k16.row.col.f32.bf16.bf16.f32 "
        "{%0,%1,%2,%3}, {%4,%5,%6,%7}, {%8,%9}, {%0,%1,%2,%3};"
        : "+f"(d[0]), "+f"(d[1]), "+f"(d[2]), "+f"(d[3])
        : "r"(a[0]), "r"(a[1]), "r"(a[2]), "r"(a[3]), "r"(b[0]), "r"(b[1]));
}

// ------------------------- prep kernels -------------------------
// weight planes: [kk][n], 128B rows, 16B chunk index XOR (kk & 7); hi/lo split
__global__ void kprep_conv(const float* w0, const float* w1, const float* w2,
                           const float* w3, const float* w4, const float* w5,
                           const float* w6, const float* w7) {
    int e = blockIdx.x * 256 + threadIdx.x;
    const int per = 27 * 4096;
    if (e >= 8 * per) return;
    int ti = e / per;
    int r  = e % per;
    int k  = r >> 12;
    int p  = r & 4095;
    int kk = p >> 6;
    int n  = p & 63;
    const float* ws[8] = {w0, w1, w2, w3, w4, w5, w6, w7};
    float v = ws[ti][(size_t)k * 4096 + kk * 64 + n];
    __nv_bfloat16 bh = __float2bfloat16_rn(v);
    __nv_bfloat16 bl = __float2bfloat16_rn(v - __bfloat162float(bh));
    int off = kk * 128 + (((n >> 3) ^ (kk & 7)) << 4) + (n & 7) * 2;
    size_t base = ((size_t)ti * 27 + k) * 8192;
    *(__nv_bfloat16*)((char*)g_wch + base + off) = bh;
    *(__nv_bfloat16*)((char*)g_wcl + base + off) = bl;
}

__global__ void kprep_dense(const float* w0, const float* w1,
                            const float* w2, const float* w3) {
    int e = blockIdx.x * 256 + threadIdx.x;
    if (e >= 4 * 4096) return;
    int ti = e >> 12;
    int p  = e & 4095;
    int kk = p >> 6;
    int n  = p & 63;
    const float* ws[4] = {w0, w1, w2, w3};
    float v = ws[ti][kk * 64 + n];
    __nv_bfloat16 bh = __float2bfloat16_rn(v);
    __nv_bfloat16 bl = __float2bfloat16_rn(v - __bfloat162float(bh));
    int off = kk * 128 + (((n >> 3) ^ (kk & 7)) << 4) + (n & 7) * 2;
    size_t base = (size_t)ti * 8192;
    *(__nv_bfloat16*)((char*)g_wdh + base + off) = bh;
    *(__nv_bfloat16*)((char*)g_wdl + base + off) = bl;
}

__global__ void kprep_idx(const int* __restrict__ idx, int N) {
    int e = blockIdx.x * 256 + threadIdx.x;
    if (e >= N * KNB) return;
    int n = e / KNB, k = e % KNB;
    g_idxT[(size_t)k * N + n] = idx[e];
}

// x2 (cols 64..127 of x, stride 128) -> bf16 hi/lo table
__global__ void kprep_x2(const float* __restrict__ x, int N) {
    int e = blockIdx.x * 256 + threadIdx.x;
    if (e >= N * 32) return;
    int n = e >> 5, c = (e & 31) * 2;
    float v0 = x[(size_t)n * 128 + 64 + c];
    float v1 = x[(size_t)n * 128 + 64 + c + 1];
    uint32_t hp = pack_bf2(v0, v1);
    uint32_t lp = pack_bf2(v0 - bflo_f(hp), v1 - bfhi_f(hp));
    *(uint32_t*)(g_x2b + (size_t)n * 256 + c * 2) = hp;
    *(uint32_t*)(g_x2b + (size_t)n * 256 + 128 + c * 2) = lp;
}

// ------------------------- cp.async staging (256 threads) -----------------
// gather 128 bf16 rows (hi+lo) into swizzled A tile pair; 2 threads per row
__device__ __forceinline__ void gather_cp(uint32_t dH, uint32_t dL,
    const char* __restrict__ tab, const int* __restrict__ idxT,
    int k, int nbase, int N, int t)
{
    int row = t >> 1, h = t & 1;
    int n = nbase + row; if (n >= N) n = N - 1;
    size_t g = (size_t)idxT[(size_t)k * N + n] * 256;
#pragma unroll
    for (int c = 0; c < 4; ++c) {
        int chunk = h * 4 + c;
        int sw = row * 128 + ((chunk ^ (row & 7)) << 4);
        cp16(dH + sw, tab + g + chunk * 16);
        cp16(dL + sw, tab + g + 128 + chunk * 16);
    }
}
// dual-table gather (shared index)
__device__ __forceinline__ void gather2_cp(uint32_t dGH, uint32_t dGL,
    uint32_t dHH, uint32_t dHL,
    const char* __restrict__ tg, const char* __restrict__ th,
    const int* __restrict__ idxT, int k, int nbase, int N, int t)
{
    int row = t >> 1, h = t & 1;
    int n = nbase + row; if (n >= N) n = N - 1;
    size_t g = (size_t)idxT[(size_t)k * N + n] * 256;
#pragma unroll
    for (int c = 0; c < 4; ++c) {
        int chunk = h * 4 + c;
        int sw = row * 128 + ((chunk ^ (row & 7)) << 4);
        cp16(dGH + sw, tg + g + chunk * 16);
        cp16(dGL + sw, tg + g + 128 + chunk * 16);
        cp16(dHH + sw, th + g + chunk * 16);
        cp16(dHL + sw, th + g + 128 + chunk * 16);
    }
}
// stage 4 pre-swizzled 8KB weight planes (gh, gl, hh, hl) -> dst..dst+32KB
__device__ __forceinline__ void stageW_cp(uint32_t dst,
    const __nv_bfloat16* gh, const __nv_bfloat16* gl,
    const __nv_bfloat16* hh, const __nv_bfloat16* hl, int t)
{
    cp16(dst + t * 16,          (const char*)gh + t * 16);
    cp16(dst + 4096 + t * 16,   (const char*)gh + 4096 + t * 16);
    cp16(dst + 8192 + t * 16,   (const char*)gl + t * 16);
    cp16(dst + 12288 + t * 16,  (const char*)gl + 4096 + t * 16);
    cp16(dst + 16384 + t * 16,  (const char*)hh + t * 16);
    cp16(dst + 20480 + t * 16,  (const char*)hh + 4096 + t * 16);
    cp16(dst + 24576 + t * 16,  (const char*)hl + t * 16);
    cp16(dst + 28672 + t * 16,  (const char*)hl + 4096 + t * 16);
}

// ------------------------- MMA core (round-4 verified) -------------------
__device__ __forceinline__ void mma_block(float acc[2][8][4],
    uint32_t aHi, uint32_t aLo, uint32_t bHi, uint32_t bLo,
    int wl, int lr, int lc)
{
    const int arow = (wl * 32 + lr) * 128;
    const int axor = lr & 7;
#pragma unroll
    for (int ks = 0; ks < 4; ++ks) {
        uint32_t ah[2][4], al[2][4];
        const int ac = ((ks * 2 + lc) ^ axor) << 4;
#pragma unroll
        for (int mt = 0; mt < 2; ++mt) {
            uint32_t ad = arow + mt * 2048 + ac;
            ldsm4(ah[mt], aHi + ad);
            ldsm4(al[mt], aLo + ad);
        }
        const int brow = ks * 2048 + lr * 128;
#pragma unroll
        for (int np = 0; np < 4; ++np) {
            uint32_t bd = brow + (((2 * np + lc) ^ axor) << 4);
            uint32_t bh[4], bl[4];
            ldsm4t(bh, bHi + bd);
            ldsm4t(bl, bLo + bd);
#pragma unroll
            for (int mt = 0; mt < 2; ++mt) {
#pragma unroll
                for (int j = 0; j < 2; ++j) {
                    float* d = acc[mt][np * 2 + j];
                    mma_bf16(d, ah[mt], &bh[j * 2]);
                    mma_bf16(d, al[mt], &bh[j * 2]);
                    mma_bf16(d, ah[mt], &bl[j * 2]);
                }
            }
        }
    }
}

// write lrelu(acc) as bf16 hi/lo swizzled A tiles (smem)
__device__ __forceinline__ void acc_to_tiles(char* sm, int baseH, int baseL,
    float acc[2][8][4], int wl, int gID, int tig)
{
#pragma unroll
    for (int mt = 0; mt < 2; ++mt) {
        int r0 = wl * 32 + mt * 16 + gID;
        int r1 = r0 + 8;
#pragma unroll
        for (int nt = 0; nt < 8; ++nt) {
            float e0 = lrelu(acc[mt][nt][0]), e1 = lrelu(acc[mt][nt][1]);
            float e2 = lrelu(acc[mt][nt][2]), e3 = lrelu(acc[mt][nt][3]);
            uint32_t h0 = pack_bf2(e0, e1);
            uint32_t l0 = pack_bf2(e0 - bflo_f(h0), e1 - bfhi_f(h0));
            uint32_t h1 = pack_bf2(e2, e3);
            uint32_t l1 = pack_bf2(e2 - bflo_f(h1), e3 - bfhi_f(h1));
            int b0 = r0 * 128 + ((nt ^ (r0 & 7)) << 4) + tig * 4;
            int b1 = r1 * 128 + ((nt ^ (r1 & 7)) << 4) + tig * 4;
            *(uint32_t*)(sm + baseH + b0) = h0;
            *(uint32_t*)(sm + baseL + b0) = l0;
            *(uint32_t*)(sm + baseH + b1) = h1;
            *(uint32_t*)(sm + baseL + b1) = l1;
        }
    }
}

// ---------------------------------------------------------------------------
// kconvA: hidden_b = lrelu( lrelu( sum_k gather(srcTab) @ W1_b[k] ) @ W2_b ),
// b in {g,h}; warps 0-3 g, 4-7 h; gather SHARED. Outputs bf16 hi/lo tables.
// ---------------------------------------------------------------------------
__global__ __launch_bounds__(256, 2)
void kconvA_mma(const char* __restrict__ srcTab, const int* __restrict__ idxT,
                const __nv_bfloat16* w1gh, const __nv_bfloat16* w1gl,
                const __nv_bfloat16* w1hh, const __nv_bfloat16* w1hl,
                const __nv_bfloat16* w2gh, const __nv_bfloat16* w2gl,
                const __nv_bfloat16* w2hh, const __nv_bfloat16* w2hl,
                char* __restrict__ outgb, char* __restrict__ outhb, int N)
{
    extern __shared__ char sm[];
    const uint32_t sb = smem_u32(sm);
    const int t = threadIdx.x;
    const int lane = t & 31, w = t >> 5;
    const int b = w >> 2, wl = w & 3;
    const int lr = ((lane >> 3) & 1) * 8 + (lane & 7);
    const int lc = lane >> 4;
    const int gID = lane >> 2, tig = lane & 3;
    const int nbase = blockIdx.x * TM;

    float acc[2][8][4];
#pragma unroll
    for (int mt = 0; mt < 2; ++mt)
#pragma unroll
        for (int nt = 0; nt < 8; ++nt)
#pragma unroll
            for (int q = 0; q < 4; ++q) acc[mt][nt][q] = 0.f;

    for (int k = 0; k < KNB; ++k) {
        __syncthreads();
        gather_cp(sb + OFF_AH, sb + OFF_AL, srcTab, idxT, k, nbase, N, t);
        stageW_cp(sb + OFF_W, w1gh + k * 4096, w1gl + k * 4096,
                  w1hh + k * 4096, w1hl + k * 4096, t);
        CP_COMMIT();
        CP_WAIT0();
        __syncthreads();
        mma_block(acc, sb + OFF_AH, sb + OFF_AL,
                  sb + OFF_W + b * 16384, sb + OFF_W + b * 16384 + 8192,
                  wl, lr, lc);
    }

    // hidden = lrelu(conv1): g -> A tiles, h -> B tiles; stage W2 planes
    __syncthreads();
    acc_to_tiles(sm, b ? OFF_BH : OFF_AH, b ? OFF_BL : OFF_AL, acc, wl, gID, tig);
    stageW_cp(sb + OFF_W, w2gh, w2gl, w2hh, w2hl, t);
    CP_COMMIT();
    CP_WAIT0();
    __syncthreads();

#pragma unroll
    for (int mt = 0; mt < 2; ++mt)
#pragma unroll
        for (int nt = 0; nt < 8; ++nt)
#pragma unroll
            for (int q = 0; q < 4; ++q) acc[mt][nt][q] = 0.f;

    mma_block(acc, sb + (b ? OFF_BH : OFF_AH), sb + (b ? OFF_BL : OFF_AL),
              sb + OFF_W + b * 16384, sb + OFF_W + b * 16384 + 8192,
              wl, lr, lc);

    // store lrelu(hidden2) as bf16 hi/lo table (256B rows)
    char* outb = b ? outhb : outgb;
#pragma unroll
    for (int mt = 0; mt < 2; ++mt) {
        int n0 = nbase + wl * 32 + mt * 16 + gID;
        int n1 = n0 + 8;
#pragma unroll
        for (int nt = 0; nt < 8; ++nt) {
            int c = nt * 8 + tig * 2;
            float e0 = lrelu(acc[mt][nt][0]), e1 = lrelu(acc[mt][nt][1]);
            float e2 = lrelu(acc[mt][nt][2]), e3 = lrelu(acc[mt][nt][3]);
            if (n0 < N) {
                uint32_t hp = pack_bf2(e0, e1);
                uint32_t lp = pack_bf2(e0 - bflo_f(hp), e1 - bfhi_f(hp));
                *(uint32_t*)(outb + (size_t)n0 * 256 + c * 2) = hp;
                *(uint32_t*)(outb + (size_t)n0 * 256 + 128 + c * 2) = lp;
            }
            if (n1 < N) {
                uint32_t hp = pack_bf2(e2, e3);
                uint32_t lp = pack_bf2(e2 - bflo_f(hp), e3 - bfhi_f(hp));
                *(uint32_t*)(outb + (size_t)n1 * 256 + c * 2) = hp;
                *(uint32_t*)(outb + (size_t)n1 * 256 + 128 + c * 2) = lp;
            }
        }
    }
}

// ---------------------------------------------------------------------------
// kconvB: G = sum_k gather(tg) @ W3g[k], H = sum_k gather(th) @ W3h[k]
// out[n,c] = xpart[n,c] * exp(tanh(G/2)) + H (stride 128); optional bf16 copy
// ---------------------------------------------------------------------------
__global__ __launch_bounds__(256, 2)
void kconvB_mma(const char* __restrict__ tg, const char* __restrict__ th,
                const int* __restrict__ idxT,
                const __nv_bfloat16* w3gh, const __nv_bfloat16* w3gl,
                const __nv_bfloat16* w3hh, const __nv_bfloat16* w3hl,
                const float* __restrict__ xpart,
                float* __restrict__ outp, char* __restrict__ bfout, int N)
{
    extern __shared__ char sm[];
    const uint32_t sb = smem_u32(sm);
    const int t = threadIdx.x;
    const int lane = t & 31, w = t >> 5;
    const int b = w >> 2, wl = w & 3;
    const int lr = ((lane >> 3) & 1) * 8 + (lane & 7);
    const int lc = lane >> 4;
    const int gID = lane >> 2, tig = lane & 3;
    const int nbase = blockIdx.x * TM;

    float acc[2][8][4];
#pragma unroll
    for (int mt = 0; mt < 2; ++mt)
#pragma unroll
        for (int nt = 0; nt < 8; ++nt)
#pragma unroll
            for (int q = 0; q < 4; ++q) acc[mt][nt][q] = 0.f;

    const uint32_t aHi = sb + (b ? OFF_BH : OFF_AH);
    const uint32_t aLo = sb + (b ? OFF_BL : OFF_AL);

    for (int k = 0; k < KNB; ++k) {
        __syncthreads();
        gather2_cp(sb + OFF_AH, sb + OFF_AL, sb + OFF_BH, sb + OFF_BL,
                   tg, th, idxT, k, nbase, N, t);
        stageW_cp(sb + OFF_W, w3gh + k * 4096, w3gl + k * 4096,
                  w3hh + k * 4096, w3hl + k * 4096, t);
        CP_COMMIT();
        CP_WAIT0();
        __syncthreads();
        mma_block(acc, aHi, aLo,
                  sb + OFF_W + b * 16384, sb + OFF_W + b * 16384 + 8192,
                  wl, lr, lc);
    }

    // epilogue: h warps publish H f32 (stride-68) into smem; g warps combine
    __syncthreads();
    float* hs = (float*)sm;
    if (b == 1) {
#pragma unroll
        for (int mt = 0; mt < 2; ++mt) {
            int r0 = wl * 32 + mt * 16 + gID;
            int r1 = r0 + 8;
#pragma unroll
            for (int nt = 0; nt < 8; ++nt) {
                int c = nt * 8 + tig * 2;
                *(float2*)(hs + r0 * 68 + c) = make_float2(acc[mt][nt][0], acc[mt][nt][1]);
                *(float2*)(hs + r1 * 68 + c) = make_float2(acc[mt][nt][2], acc[mt][nt][3]);
            }
        }
    }
    __syncthreads();
    if (b == 0) {
#pragma unroll
        for (int mt = 0; mt < 2; ++mt) {
#pragma unroll
            for (int half = 0; half < 2; ++half) {
                int r = wl * 32 + mt * 16 + half * 8 + gID;
                int n = nbase + r;
                if (n >= N) continue;
#pragma unroll
                for (int nt = 0; nt < 8; ++nt) {
                    int c = nt * 8 + tig * 2;
                    float g0 = acc[mt][nt][half * 2 + 0];
                    float g1 = acc[mt][nt][half * 2 + 1];
                    float2 hv = *(const float2*)(hs + r * 68 + c);
                    float2 xv = *(const float2*)(xpart + (size_t)n * 128 + c);
                    float2 y;
                    y.x = fmaf(xv.x, expf(tanhf(0.5f * g0)), hv.x);
                    y.y = fmaf(xv.y, expf(tanhf(0.5f * g1)), hv.y);
                    *(float2*)(outp + (size_t)n * 128 + c) = y;
                    if (bfout) {
                        uint32_t hp = pack_bf2(y.x, y.y);
                        uint32_t lp = pack_bf2(y.x - bflo_f(hp), y.y - bfhi_f(hp));
                        *(uint32_t*)(bfout + (size_t)n * 256 + c * 2) = hp;
                        *(uint32_t*)(bfout + (size_t)n * 256 + 128 + c * 2) = lp;
                    }
                }
            }
        }
    }
}

// ---------------------------------------------------------------------------
extern "C" void kernel_launch(void* const* d_in, const int* in_sizes, int n_in,
                              void* d_out, int out_size)
{
    const float* x     = (const float*)d_in[0];
    const int*   nbr   = (const int*)d_in[1];
    const float* g1_w1 = (const float*)d_in[2];
    const float* g1_w2 = (const float*)d_in[3];
    const float* g1_w3 = (const float*)d_in[4];
    const float* g2_w1 = (const float*)d_in[5];
    const float* g2_w2 = (const float*)d_in[6];
    const float* g2_w3 = (const float*)d_in[7];
    const float* h1_w1 = (const float*)d_in[8];
    const float* h1_w2 = (const float*)d_in[9];
    const float* h1_w3 = (const float*)d_in[10];
    const float* h2_w1 = (const float*)d_in[11];
    const float* h2_w2 = (const float*)d_in[12];
    const float* h2_w3 = (const float*)d_in[13];
    float* out = (float*)d_out;

    const int N = in_sizes[1] / KNB;
    const int blocks = (N + TM - 1) / TM;

    cudaFuncSetAttribute(kconvA_mma, cudaFuncAttributeMaxDynamicSharedMemorySize, SMEM_BYTES);
    cudaFuncSetAttribute(kconvB_mma, cudaFuncAttributeMaxDynamicSharedMemorySize, SMEM_BYTES);

    __nv_bfloat16 *wch, *wcl, *wdh, *wdl;
    cudaGetSymbolAddress((void**)&wch, g_wch);
    cudaGetSymbolAddress((void**)&wcl, g_wcl);
    cudaGetSymbolAddress((void**)&wdh, g_wdh);
    cudaGetSymbolAddress((void**)&wdl, g_wdl);
    int* idxT;   cudaGetSymbolAddress((void**)&idxT, g_idxT);
    char *x2b, *hgb, *hhb, *y1b;
    cudaGetSymbolAddress((void**)&x2b, g_x2b);
    cudaGetSymbolAddress((void**)&hgb, g_hgb);
    cudaGetSymbolAddress((void**)&hhb, g_hhb);
    cudaGetSymbolAddress((void**)&y1b, g_y1b);

    // conv tensor order: 0:g2w1 1:h2w1 2:g2w3 3:h2w3 4:g1w1 5:h1w1 6:g1w3 7:h1w3
    kprep_conv<<<(8 * 27 * 4096 + 255) / 256, 256>>>(
        g2_w1, h2_w1, g2_w3, h2_w3, g1_w1, h1_w1, g1_w3, h1_w3);
    // dense order: 0:g2w2 1:h2w2 2:g1w2 3:h1w2
    kprep_dense<<<(4 * 4096 + 255) / 256, 256>>>(g2_w2, h2_w2, g1_w2, h1_w2);
    kprep_idx<<<(N * KNB + 255) / 256, 256>>>(nbr, N);
    kprep_x2<<<(N * 32 + 255) / 256, 256>>>(x, N);

    const int CP = 27 * 4096;   // bf16 elems per conv tensor

    // Stage 1: bottlenecks g2/h2 on x2 table (shared gather)
    kconvA_mma<<<blocks, 256, SMEM_BYTES>>>(
        x2b, idxT,
        wch + 0 * CP, wcl + 0 * CP, wch + 1 * CP, wcl + 1 * CP,
        wdh + 0 * 4096, wdl + 0 * 4096, wdh + 1 * 4096, wdl + 1 * 4096,
        hgb, hhb, N);
    // y1 = x1 * exp(tanh(G/2)) + H -> out[:, 0:64] (+ bf16 table for stage 2)
    kconvB_mma<<<blocks, 256, SMEM_BYTES>>>(
        hgb, hhb, idxT,
        wch + 2 * CP, wcl + 2 * CP, wch + 3 * CP, wcl + 3 * CP,
        x /*x1*/, out /*y1*/, y1b, N);
    // Stage 2: bottlenecks g1/h1 on y1 table
    kconvA_mma<<<blocks, 256, SMEM_BYTES>>>(
        y1b, idxT,
        wch + 4 * CP, wcl + 4 * CP, wch + 5 * CP, wcl + 5 * CP,
        wdh + 2 * 4096, wdl + 2 * 4096, wdh + 3 * 4096, wdl + 3 * 4096,
        hgb, hhb, N);
    // y2 = x2 * exp(tanh(G2/2)) + H2 -> out[:, 64:128]
    kconvB_mma<<<blocks, 256, SMEM_BYTES>>>(
        hgb, hhb, idxT,
        wch + 6 * CP, wcl + 6 * CP, wch + 7 * CP, wcl + 7 * CP,
        x + 64 /*x2*/, out + 64 /*y2*/, nullptr, N);
}